// round 2
// baseline (speedup 1.0000x reference)
#include <cuda_runtime.h>
#include <math.h>

// Problem constants (fixed shapes)
#define NTOK 2048
#define NH   8
#define HD   128
#define NN   32     // neighbors
#define NJ   34     // 2 + NN
#define D0   128
#define D1   64

#define SCALE0  0.25f                  // 1/sqrt(16)
#define SCALE1  0.14433756729740643f   // 1/sqrt(48)
#define SHAREDC 0.70710678118654752f   // sqrt(0.5)
#define NEGV    -1e9f

// ---------------- scratch (no allocation allowed) ----------------
__device__ float g_skv0[NTOK * 256];        // self k|v deg0: rows 0..127 = k, 128..255 = v
__device__ float g_skv1[NTOK * 256 * 3];    // self k|v deg1, layout (i, o, m)
__device__ float g_out0[NTOK * 128];
__device__ float g_out1[NTOK * 384];        // (i, c, m) merged-head layout
__device__ int   g_mask_mode;               // 0=byte, 1=int32, 2=float32

// ---------------- mask dtype detection ----------------
__global__ void detect_mask_kernel(const unsigned int* __restrict__ m) {
    int allBin = 1, allFloat = 1;
    for (int k = 0; k < 128; k++) {           // 512 bytes: safe under all layouts
        unsigned v = m[k];
        if (v != 0u && v != 1u) allBin = 0;
        if (v != 0u && v != 0x3F800000u) allFloat = 0;
    }
    g_mask_mode = allBin ? 1 : (allFloat ? 2 : 0);
}

// ---------------- generic tiled SGEMM: C = A * B^T ----------------
// A: M x K with row stride lda, element stride eA (for m-sliced tensors), base += blockIdx.z
// B: N x K row-major (weights)
// C: row stride ldc, element stride eC, base += blockIdx.z
// grid: (N/64, M/64, Z). M, N multiples of 64; K multiple of 16 (true for all launches).
#define BM 64
#define BN 64
#define BK 16
__global__ __launch_bounds__(256) void gemm_tn(
    const float* __restrict__ A, const float* __restrict__ B, float* __restrict__ C,
    int K, int lda, int eA, int ldc, int eC)
{
    A += blockIdx.z;
    C += blockIdx.z;
    const int m0 = blockIdx.y * BM;
    const int n0 = blockIdx.x * BN;
    __shared__ __align__(16) float As[BK][BM + 4];
    __shared__ __align__(16) float Bs[BK][BN + 4];

    const int t  = threadIdx.x;
    const int tx = t & 15;     // n dim
    const int ty = t >> 4;     // m dim
    float acc[4][4] = {};

    for (int k0 = 0; k0 < K; k0 += BK) {
        #pragma unroll
        for (int l = t; l < BM * BK; l += 256) {
            int mi = l >> 4, kk = l & 15;
            As[kk][mi] = A[(size_t)(m0 + mi) * lda + (size_t)(k0 + kk) * eA];
        }
        #pragma unroll
        for (int l = t; l < BN * BK; l += 256) {
            int ni = l >> 4, kk = l & 15;
            Bs[kk][ni] = B[(size_t)(n0 + ni) * K + (k0 + kk)];
        }
        __syncthreads();
        #pragma unroll
        for (int kk = 0; kk < BK; kk++) {
            float4 a = *(const float4*)&As[kk][ty * 4];
            float4 b = *(const float4*)&Bs[kk][tx * 4];
            float av[4] = {a.x, a.y, a.z, a.w};
            float bv[4] = {b.x, b.y, b.z, b.w};
            #pragma unroll
            for (int r = 0; r < 4; r++)
                #pragma unroll
                for (int s = 0; s < 4; s++)
                    acc[r][s] = fmaf(av[r], bv[s], acc[r][s]);
        }
        __syncthreads();
    }
    #pragma unroll
    for (int r = 0; r < 4; r++)
        #pragma unroll
        for (int s = 0; s < 4; s++)
            C[(size_t)(m0 + ty * 4 + r) * ldc + (size_t)(n0 + tx * 4 + s) * eC] = acc[r][s];
}

// ---------------- main attention kernel: one token per block ----------------
__global__ __launch_bounds__(256) void attn_kernel(
    const float* __restrict__ q0, const float* __restrict__ q1,
    const float* __restrict__ k0, const float* __restrict__ k1,
    const float* __restrict__ v0, const float* __restrict__ v1,
    const float* __restrict__ edges, const float* __restrict__ wbias,
    const float* __restrict__ self_bias, const float* __restrict__ null_bias,
    const float* __restrict__ nk0, const float* __restrict__ nv0,
    const float* __restrict__ nk1, const float* __restrict__ nv1,
    const float* __restrict__ hw1, const void* __restrict__ nbmask)
{
    const int i = blockIdx.x;
    const int t = threadIdx.x;

    __shared__ __align__(16) float q0s[128];
    __shared__ __align__(16) float q1s[384];
    __shared__ float edg[32 * 33];   // padded to kill bank conflicts
    __shared__ float wb[256];
    __shared__ float w1s[8], sb[8], nb[8];
    __shared__ float totS[NH * NJ];
    __shared__ float attnS[NH * NJ];

    // ---- stage ----
    if (t < 128) q0s[t] = q0[(size_t)i * 128 + t];
    for (int l = t; l < 384; l += 256) q1s[l] = q1[(size_t)i * 384 + l];
    for (int l = t; l < 1024; l += 256) {
        int j = l >> 5, e = l & 31;
        edg[j * 33 + e] = edges[(size_t)i * 1024 + l];
    }
    wb[t] = wbias[t];
    if (t < 8) {
        float x = hw1[t];
        float sp = (x > 20.f) ? x : log1pf(__expf(x));
        w1s[t] = sp * SCALE1;
        sb[t] = self_bias[t];
        nb[t] = null_bias[t];
    }
    __syncthreads();

    const int mmode = g_mask_mode;

    // ---- logits: 272 items (h, j) ----
    for (int idx = t; idx < NH * NJ; idx += 256) {
        const int h = idx / NJ;
        const int j = idx - h * NJ;
        const float* kp0;
        const float* kp1;
        float bias;
        bool valid = true;
        if (j >= 2) {
            size_t r = (size_t)i * NN + (j - 2);
            kp0 = k0 + r * 128 + h * 16;
            kp1 = k1 + r * 384 + h * 48;
            float eb = 0.f;
            #pragma unroll
            for (int e = 0; e < 32; e++)
                eb = fmaf(edg[(j - 2) * 33 + e], wb[h * 32 + e], eb);
            bias = eb;
            int mi = i * NN + (j - 2);
            if (mmode == 1)      valid = ((const int*)nbmask)[mi] != 0;
            else if (mmode == 2) valid = ((const float*)nbmask)[mi] != 0.f;
            else                 valid = ((const unsigned char*)nbmask)[mi] != 0;
        } else if (j == 1) {
            kp0 = g_skv0 + (size_t)i * 256 + h * 16;
            kp1 = g_skv1 + (size_t)i * 768 + h * 48;
            bias = sb[h];
        } else {
            kp0 = nk0 + h * 16;
            kp1 = nk1 + h * 48;
            bias = nb[h];
        }
        float s0 = 0.f, s1 = 0.f;
        const float4* qa = (const float4*)(q0s + h * 16);
        const float4* ka = (const float4*)kp0;
        #pragma unroll
        for (int d = 0; d < 4; d++) {
            float4 qv = qa[d], kv = ka[d];
            s0 += qv.x * kv.x + qv.y * kv.y + qv.z * kv.z + qv.w * kv.w;
        }
        const float4* qb = (const float4*)(q1s + h * 48);
        const float4* kb = (const float4*)kp1;
        #pragma unroll
        for (int d = 0; d < 12; d++) {
            float4 qv = qb[d], kv = kb[d];
            s1 += qv.x * kv.x + qv.y * kv.y + qv.z * kv.z + qv.w * kv.w;
        }
        float tot = (s0 * SCALE0 + bias + s1 * w1s[h]) * SHAREDC;
        totS[idx] = valid ? tot : NEGV;
    }
    __syncthreads();

    // ---- softmax: warp w handles head w over 34 logits ----
    {
        const int w = t >> 5, lane = t & 31;
        float x1 = totS[w * NJ + lane];
        float x2 = (lane < 2) ? totS[w * NJ + 32 + lane] : -2e9f;
        float mx = fmaxf(x1, x2);
        #pragma unroll
        for (int o = 16; o > 0; o >>= 1) mx = fmaxf(mx, __shfl_xor_sync(0xffffffffu, mx, o));
        float e1 = __expf(x1 - mx);
        float e2 = (lane < 2) ? __expf(x2 - mx) : 0.f;
        float s = e1 + e2;
        #pragma unroll
        for (int o = 16; o > 0; o >>= 1) s += __shfl_xor_sync(0xffffffffu, s, o);
        float inv = 1.f / s;
        attnS[w * NJ + lane] = e1 * inv;
        if (lane < 2) attnS[w * NJ + 32 + lane] = e2 * inv;
    }
    __syncthreads();

    // ---- weighted V accumulation ----
    float a0 = 0.f, a1 = 0.f, a1b = 0.f;
    const int h0 = (t < 128) ? (t >> 4) : 0;
    const int ha = t / 48;          // head of deg1 element t       (t < 256 -> <= 5)
    const int hb = (t + 256) / 48;  // head of deg1 element t+256   (t < 128 -> <= 7)
    #pragma unroll 1
    for (int j = 0; j < NJ; j++) {
        const float* v0p;
        const float* v1p;
        if (j >= 2) {
            size_t r = (size_t)i * NN + (j - 2);
            v0p = v0 + r * 128;
            v1p = v1 + r * 384;
        } else if (j == 1) {
            v0p = g_skv0 + (size_t)i * 256 + 128;
            v1p = g_skv1 + (size_t)i * 768 + 384;
        } else {
            v0p = nv0;
            v1p = nv1;
        }
        if (t < 128) a0 = fmaf(attnS[h0 * NJ + j], v0p[t], a0);
        a1 = fmaf(attnS[ha * NJ + j], v1p[t], a1);
        if (t < 128) a1b = fmaf(attnS[hb * NJ + j], v1p[256 + t], a1b);
    }
    if (t < 128) g_out0[(size_t)i * 128 + t] = a0;
    g_out1[(size_t)i * 384 + t] = a1;
    if (t < 128) g_out1[(size_t)i * 384 + 256 + t] = a1b;
}

// ---------------- launch ----------------
extern "C" void kernel_launch(void* const* d_in, const int* in_sizes, int n_in,
                              void* d_out, int out_size)
{
    const float* q0     = (const float*)d_in[0];
    const float* k0     = (const float*)d_in[1];
    const float* v0     = (const float*)d_in[2];
    const float* q1     = (const float*)d_in[3];
    const float* k1     = (const float*)d_in[4];
    const float* v1     = (const float*)d_in[5];
    const float* feats0 = (const float*)d_in[6];
    const float* feats1 = (const float*)d_in[7];
    const float* edges  = (const float*)d_in[8];
    const float* Wskv0  = (const float*)d_in[9];
    const float* Wskv1  = (const float*)d_in[10];
    const float* Wbias  = (const float*)d_in[11];
    const float* sbias  = (const float*)d_in[12];
    const float* nbias  = (const float*)d_in[13];
    const float* nk0    = (const float*)d_in[14];
    const float* nv0    = (const float*)d_in[15];
    const float* nk1    = (const float*)d_in[16];
    const float* nv1    = (const float*)d_in[17];
    const float* hw1    = (const float*)d_in[18];
    const float* Wout0  = (const float*)d_in[19];
    const float* Wout1  = (const float*)d_in[20];
    const void*  nbm    = d_in[21];
    float* out = (float*)d_out;

    void *p_skv0, *p_skv1, *p_out0, *p_out1;
    cudaGetSymbolAddress(&p_skv0, g_skv0);
    cudaGetSymbolAddress(&p_skv1, g_skv1);
    cudaGetSymbolAddress(&p_out0, g_out0);
    cudaGetSymbolAddress(&p_out1, g_out1);

    detect_mask_kernel<<<1, 1>>>((const unsigned int*)nbm);

    // self-KV deg0: (2048x256) = feats0(2048x128) * W_self_kv0^T(256x128)
    gemm_tn<<<dim3(256 / BN, NTOK / BM, 1), 256>>>(
        feats0, Wskv0, (float*)p_skv0, 128, /*lda*/128, /*eA*/1, /*ldc*/256, /*eC*/1);

    // self-KV deg1, per m-slice (z=0..2): (2048x256) = feats1_m(2048x64) * W_self_kv1^T(256x64)
    gemm_tn<<<dim3(256 / BN, NTOK / BM, 3), 256>>>(
        feats1, Wskv1, (float*)p_skv1, 64, /*lda*/192, /*eA*/3, /*ldc*/768, /*eC*/3);

    // attention core
    attn_kernel<<<NTOK, 256>>>(q0, q1, k0, k1, v0, v1, edges, Wbias,
                               sbias, nbias, nk0, nv0, nk1, nv1, hw1, nbm);

    // y0 = out0 * W_out0^T  -> d_out[0 .. 2048*128)
    gemm_tn<<<dim3(128 / BN, NTOK / BM, 1), 256>>>(
        (const float*)p_out0, Wout0, out, 128, /*lda*/128, /*eA*/1, /*ldc*/128, /*eC*/1);

    // y1_m = out1_m * W_out1^T -> d_out[2048*128 ..), layout (i, o, m)
    gemm_tn<<<dim3(64 / BN, NTOK / BM, 3), 256>>>(
        (const float*)p_out1, Wout1, out + (size_t)NTOK * 128, 128,
        /*lda*/384, /*eA*/3, /*ldc*/192, /*eC*/3);
}

// round 3
// speedup vs baseline: 1.4094x; 1.4094x over previous
#include <cuda_runtime.h>
#include <math.h>

#define NTOK 2048
#define NH   8
#define NN   32
#define NJ   34

#define SCALE0  0.25f
#define SCALE1  0.14433756729740643f
#define SHAREDC 0.70710678118654752f
#define NEGV    -1e9f

// ---------------- scratch ----------------
__device__ float g_skv0[NTOK * 256];       // rows: [0..128)=k_self, [128..256)=v_self
__device__ float g_skv1[NTOK * 768];       // (i, o, m): o<128 k, o>=128 v
__device__ float g_out0[NTOK * 128];
__device__ float g_out1[NTOK * 384];       // (i, c, m)
__device__ int   g_mask_mode;              // 0=byte, 1=int32, 2=float32

__device__ __forceinline__ float dot4(float4 a, float4 b) {
    return a.x*b.x + a.y*b.y + a.z*b.z + a.w*b.w;
}

// ---------------- fused tiled SGEMM (C = A * B^T), double buffered ----------------
#define BM 64
#define BN 64
#define BK 16

struct GemmArgs {
    const float* A; const float* B; float* C;
    int K, lda, eA, ldc, eC;
};

__device__ __forceinline__ void gemm_body(
    const GemmArgs& g, int m0, int n0,
    float (*As)[BK][BM + 4], float (*Bs)[BK][BN + 4])
{
    const int t  = threadIdx.x;
    const int tx = t & 15;
    const int ty = t >> 4;
    const int aM = t >> 4;   // 0..15
    const int aK = t & 15;

    float acc[4][4] = {};
    float ra[4], rb[4];

    #pragma unroll
    for (int r = 0; r < 4; r++) {
        ra[r] = g.A[(size_t)(m0 + aM + 16*r) * g.lda + (size_t)aK * g.eA];
        rb[r] = g.B[(size_t)(n0 + aM + 16*r) * g.K + aK];
    }

    int buf = 0;
    for (int k0 = 0; k0 < g.K; k0 += BK) {
        #pragma unroll
        for (int r = 0; r < 4; r++) {
            As[buf][aK][aM + 16*r] = ra[r];
            Bs[buf][aK][aM + 16*r] = rb[r];
        }
        __syncthreads();
        const int kn = k0 + BK;
        if (kn < g.K) {
            #pragma unroll
            for (int r = 0; r < 4; r++) {
                ra[r] = g.A[(size_t)(m0 + aM + 16*r) * g.lda + (size_t)(kn + aK) * g.eA];
                rb[r] = g.B[(size_t)(n0 + aM + 16*r) * g.K + (kn + aK)];
            }
        }
        #pragma unroll
        for (int kk = 0; kk < BK; kk++) {
            float4 a = *(const float4*)&As[buf][kk][ty * 4];
            float4 b = *(const float4*)&Bs[buf][kk][tx * 4];
            float av[4] = {a.x, a.y, a.z, a.w};
            float bv[4] = {b.x, b.y, b.z, b.w};
            #pragma unroll
            for (int r = 0; r < 4; r++)
                #pragma unroll
                for (int s = 0; s < 4; s++)
                    acc[r][s] = fmaf(av[r], bv[s], acc[r][s]);
        }
        buf ^= 1;
    }
    #pragma unroll
    for (int r = 0; r < 4; r++)
        #pragma unroll
        for (int s = 0; s < 4; s++)
            g.C[(size_t)(m0 + ty*4 + r) * g.ldc + (size_t)(n0 + tx*4 + s) * g.eC] = acc[r][s];
}

// z==0: deg0 self-kv; z in 1..3: deg1 slice (z-1). Also embeds mask detection.
__global__ __launch_bounds__(256) void skv_fused_kernel(
    const float* __restrict__ feats0, const float* __restrict__ Wskv0,
    const float* __restrict__ feats1, const float* __restrict__ Wskv1,
    const unsigned int* __restrict__ mask)
{
    if (blockIdx.z == 0 && blockIdx.x == 0 && blockIdx.y == 0 && threadIdx.x == 0) {
        int allBin = 1, allFloat = 1;
        for (int k = 0; k < 128; k++) {
            unsigned v = mask[k];
            if (v != 0u && v != 1u) allBin = 0;
            if (v != 0u && v != 0x3F800000u) allFloat = 0;
        }
        g_mask_mode = allBin ? 1 : (allFloat ? 2 : 0);
    }
    __shared__ float As[2][BK][BM + 4];
    __shared__ float Bs[2][BK][BN + 4];
    GemmArgs g;
    if (blockIdx.z == 0) {
        g = {feats0, Wskv0, g_skv0, 128, 128, 1, 256, 1};
    } else {
        int m = blockIdx.z - 1;
        g = {feats1 + m, Wskv1, g_skv1 + m, 64, 192, 3, 768, 3};
    }
    gemm_body(g, blockIdx.y * BM, blockIdx.x * BN, As, Bs);
}

// z==0: y0 (needs x=0,1); z in 1..3: y1 slice (only x==0 active)
__global__ __launch_bounds__(256) void out_fused_kernel(
    const float* __restrict__ Wout0, const float* __restrict__ Wout1,
    float* __restrict__ out)
{
    if (blockIdx.z != 0 && blockIdx.x != 0) return;
    __shared__ float As[2][BK][BM + 4];
    __shared__ float Bs[2][BK][BN + 4];
    GemmArgs g;
    if (blockIdx.z == 0) {
        g = {g_out0, Wout0, out, 128, 128, 1, 128, 1};
    } else {
        int m = blockIdx.z - 1;
        g = {g_out1 + m, Wout1, out + (size_t)NTOK * 128 + m, 128, 384, 3, 192, 3};
    }
    gemm_body(g, blockIdx.y * BM, blockIdx.x * BN, As, Bs);
}

// ---------------- attention core: one token per 256-thread block ----------------
__global__ __launch_bounds__(256) void attn_kernel(
    const float* __restrict__ q0, const float* __restrict__ q1,
    const float* __restrict__ k0, const float* __restrict__ k1,
    const float* __restrict__ v0, const float* __restrict__ v1,
    const float* __restrict__ edges, const float* __restrict__ wbias,
    const float* __restrict__ self_bias, const float* __restrict__ null_bias,
    const float* __restrict__ nk0, const float* __restrict__ nv0,
    const float* __restrict__ nk1, const float* __restrict__ nv1,
    const float* __restrict__ hw1, const void* __restrict__ nbmask)
{
    const int i = blockIdx.x;
    const int t = threadIdx.x;

    __shared__ __align__(16) float q0s[128];
    __shared__ __align__(16) float q1s[384];
    __shared__ __align__(16) float wb[256];
    __shared__ float w1s[NH], sbS[NH], nbS[NH];
    __shared__ float totS[NH * NJ];
    __shared__ float attnS[NH * NJ];
    __shared__ const float* kp0S[NJ];
    __shared__ const float* kp1S[NJ];
    __shared__ const float* vp0S[NJ];
    __shared__ const float* vp1S[NJ];
    __shared__ int validS[NJ];
    __shared__ __align__(16) float red[512];

    // ---- stage ----
    if (t < 32) {
        ((float4*)q0s)[t] = ((const float4*)(q0 + (size_t)i * 128))[t];
    } else if (t < 128) {
        ((float4*)q1s)[t - 32] = ((const float4*)(q1 + (size_t)i * 384))[t - 32];
    } else if (t < 192) {
        ((float4*)wb)[t - 128] = ((const float4*)wbias)[t - 128];
    } else if (t < 200) {
        int h = t - 192;
        float x = hw1[h];
        float sp = (x > 20.f) ? x : log1pf(__expf(x));
        w1s[h] = sp * SCALE1;
        sbS[h] = self_bias[h];
        nbS[h] = null_bias[h];
    } else if (t >= 208 && t < 208 + NJ) {
        int j = t - 208;
        if (j == 0) {
            kp0S[0] = nk0; kp1S[0] = nk1; vp0S[0] = nv0; vp1S[0] = nv1; validS[0] = 1;
        } else if (j == 1) {
            kp0S[1] = g_skv0 + (size_t)i * 256;
            vp0S[1] = g_skv0 + (size_t)i * 256 + 128;
            kp1S[1] = g_skv1 + (size_t)i * 768;
            vp1S[1] = g_skv1 + (size_t)i * 768 + 384;
            validS[1] = 1;
        } else {
            size_t r = (size_t)i * NN + (j - 2);
            kp0S[j] = k0 + r * 128;
            kp1S[j] = k1 + r * 384;
            vp0S[j] = v0 + r * 128;
            vp1S[j] = v1 + r * 384;
            int mm = g_mask_mode;
            int mi = i * NN + (j - 2);
            int valid;
            if (mm == 1)      valid = ((const int*)nbmask)[mi] != 0;
            else if (mm == 2) valid = ((const float*)nbmask)[mi] != 0.f;
            else              valid = ((const unsigned char*)nbmask)[mi] != 0;
            validS[j] = valid;
        }
    }
    __syncthreads();

    // ---- logits: warp per j; lane owns head lane/4, segment lane%4 ----
    {
        const int w = t >> 5, lane = t & 31;
        const int h = lane >> 2, part = lane & 3;
        const float4 qa = ((const float4*)q0s)[lane];
        const float4* q1v = (const float4*)(q1s + 12 * lane);
        const float4 qb0 = q1v[0], qb1 = q1v[1], qb2 = q1v[2];
        const float w1h = w1s[h];

        for (int j = w; j < NJ; j += 8) {
            const float4* k0p = (const float4*)kp0S[j];
            const float4* k1p = (const float4*)(kp1S[j] + 12 * lane);
            float4 ka  = k0p[lane];
            float4 kb0 = k1p[0], kb1 = k1p[1], kb2 = k1p[2];
            float s0 = dot4(qa, ka);
            float s1 = dot4(qb0, kb0) + dot4(qb1, kb1) + dot4(qb2, kb2);
            float p = s0 * SCALE0 + s1 * w1h;
            if (j >= 2) {
                const float4* ep  = (const float4*)(edges + (size_t)i * 1024 + (j - 2) * 32 + part * 8);
                const float4* wbp = (const float4*)(wb + h * 32 + part * 8);
                p += dot4(ep[0], wbp[0]) + dot4(ep[1], wbp[1]);
            }
            p += __shfl_down_sync(0xffffffffu, p, 2);
            p += __shfl_down_sync(0xffffffffu, p, 1);
            if (part == 0) {
                if (j == 1) p += sbS[h];
                if (j == 0) p += nbS[h];
                totS[h * NJ + j] = validS[j] ? p * SHAREDC : NEGV;
            }
        }
    }
    __syncthreads();

    // ---- softmax: warp w = head w over 34 logits ----
    {
        const int w = t >> 5, lane = t & 31;
        float x1 = totS[w * NJ + lane];
        float x2 = (lane < 2) ? totS[w * NJ + 32 + lane] : -2e9f;
        float mx = fmaxf(x1, x2);
        #pragma unroll
        for (int o = 16; o > 0; o >>= 1) mx = fmaxf(mx, __shfl_xor_sync(0xffffffffu, mx, o));
        float e1 = __expf(x1 - mx);
        float e2 = (lane < 2) ? __expf(x2 - mx) : 0.f;
        float s = e1 + e2;
        #pragma unroll
        for (int o = 16; o > 0; o >>= 1) s += __shfl_xor_sync(0xffffffffu, s, o);
        float inv = 1.f / s;
        attnS[w * NJ + lane] = e1 * inv;
        if (lane < 2) attnS[w * NJ + 32 + lane] = e2 * inv;
    }
    __syncthreads();

    // ---- V accumulation: two 128-thread halves, float4 per thread, prefetch ----
    {
        const int g  = t >> 7;        // half: even j / odd j
        const int tl = t & 127;
        const bool isV1 = (tl < 96);
        const int off = isV1 ? 4 * tl : 4 * (tl - 96);
        const int hv  = isV1 ? (tl / 12) : ((tl - 96) / 4);

        float4 acc = make_float4(0.f, 0.f, 0.f, 0.f);
        float4 cur = *(const float4*)((isV1 ? vp1S[g] : vp0S[g]) + off);
        #pragma unroll 1
        for (int j = g; j < NJ; j += 2) {
            float4 nxt = make_float4(0.f, 0.f, 0.f, 0.f);
            int jn = j + 2;
            if (jn < NJ)
                nxt = *(const float4*)((isV1 ? vp1S[jn] : vp0S[jn]) + off);
            float wgt = attnS[hv * NJ + j];
            acc.x = fmaf(wgt, cur.x, acc.x);
            acc.y = fmaf(wgt, cur.y, acc.y);
            acc.z = fmaf(wgt, cur.z, acc.z);
            acc.w = fmaf(wgt, cur.w, acc.w);
            cur = nxt;
        }
        if (g == 0) {
            ((float4*)red)[tl] = acc;
        }
        __syncthreads();
        if (g == 1) {
            float4 o = ((const float4*)red)[tl];
            acc.x += o.x; acc.y += o.y; acc.z += o.z; acc.w += o.w;
            if (isV1) *(float4*)(g_out1 + (size_t)i * 384 + off) = acc;
            else      *(float4*)(g_out0 + (size_t)i * 128 + off) = acc;
        }
    }
}

// ---------------- launch ----------------
extern "C" void kernel_launch(void* const* d_in, const int* in_sizes, int n_in,
                              void* d_out, int out_size)
{
    const float* q0     = (const float*)d_in[0];
    const float* k0     = (const float*)d_in[1];
    const float* v0     = (const float*)d_in[2];
    const float* q1     = (const float*)d_in[3];
    const float* k1     = (const float*)d_in[4];
    const float* v1     = (const float*)d_in[5];
    const float* feats0 = (const float*)d_in[6];
    const float* feats1 = (const float*)d_in[7];
    const float* edges  = (const float*)d_in[8];
    const float* Wskv0  = (const float*)d_in[9];
    const float* Wskv1  = (const float*)d_in[10];
    const float* Wbias  = (const float*)d_in[11];
    const float* sbias  = (const float*)d_in[12];
    const float* nbias  = (const float*)d_in[13];
    const float* nk0    = (const float*)d_in[14];
    const float* nv0    = (const float*)d_in[15];
    const float* nk1    = (const float*)d_in[16];
    const float* nv1    = (const float*)d_in[17];
    const float* hw1    = (const float*)d_in[18];
    const float* Wout0  = (const float*)d_in[19];
    const float* Wout1  = (const float*)d_in[20];
    const void*  nbm    = d_in[21];
    float* out = (float*)d_out;

    skv_fused_kernel<<<dim3(4, NTOK / BM, 4), 256>>>(
        feats0, Wskv0, feats1, Wskv1, (const unsigned int*)nbm);

    attn_kernel<<<NTOK, 256>>>(q0, q1, k0, k1, v0, v1, edges, Wbias,
                               sbias, nbias, nk0, nv0, nk1, nv1, hw1, nbm);

    out_fused_kernel<<<dim3(2, NTOK / BM, 4), 256>>>(Wout0, Wout1, out);
}

// round 4
// speedup vs baseline: 1.4582x; 1.0346x over previous
#include <cuda_runtime.h>
#include <math.h>

#define NTOK 2048
#define NH   8
#define NN   32
#define NJ   34

#define SCALE0  0.25f
#define SCALE1  0.14433756729740643f
#define SHAREDC 0.70710678118654752f
#define NEGV    -1e9f

// ---------------- scratch ----------------
__device__ float g_skv0[NTOK * 256];       // [0..128)=k_self, [128..256)=v_self
__device__ float g_skv1[NTOK * 768];       // (i, o, m): o<128 k, o>=128 v
__device__ float g_out0[NTOK * 128];
__device__ float g_out1[NTOK * 384];       // (i, c, m)
__device__ int   g_mask_mode;              // 0=byte, 1=int32, 2=float32

__device__ __forceinline__ float dot4(float4 a, float4 b) {
    return a.x*b.x + a.y*b.y + a.z*b.z + a.w*b.w;
}

// ---------------- tiled SGEMM (C = A * B^T): 128 thr, BM=64 x BN=32 ----------------
#define BM 64
#define BN 32
#define BK 16

template<int K>
__device__ __forceinline__ void gemm_body(
    const float* __restrict__ A, const float* __restrict__ B, float* __restrict__ C,
    int lda, int eA, int ldc, int eC, int m0, int n0,
    float (*As)[BK][BM + 4], float (*Bs)[BK][BN + 4])
{
    const int t  = threadIdx.x;      // 0..127
    const int tx = t & 7;            // 8 * 4 = 32 (n)
    const int ty = t >> 3;           // 16 * 4 = 64 (m)
    const int aK = t & 15;
    const int aM = t >> 4;           // 0..7

    float acc[4][4] = {};
    float ra[8], rb[4];

    #pragma unroll
    for (int r = 0; r < 8; r++)
        ra[r] = A[(size_t)(m0 + aM + 8*r) * lda + (size_t)aK * eA];
    #pragma unroll
    for (int r = 0; r < 4; r++)
        rb[r] = B[(size_t)(n0 + aM + 8*r) * K + aK];

    int buf = 0;
    #pragma unroll
    for (int k0 = 0; k0 < K; k0 += BK) {
        #pragma unroll
        for (int r = 0; r < 8; r++) As[buf][aK][aM + 8*r] = ra[r];
        #pragma unroll
        for (int r = 0; r < 4; r++) Bs[buf][aK][aM + 8*r] = rb[r];
        __syncthreads();
        const int kn = k0 + BK;
        if (kn < K) {
            #pragma unroll
            for (int r = 0; r < 8; r++)
                ra[r] = A[(size_t)(m0 + aM + 8*r) * lda + (size_t)(kn + aK) * eA];
            #pragma unroll
            for (int r = 0; r < 4; r++)
                rb[r] = B[(size_t)(n0 + aM + 8*r) * K + (kn + aK)];
        }
        #pragma unroll
        for (int kk = 0; kk < BK; kk++) {
            float4 a = *(const float4*)&As[buf][kk][ty * 4];
            float4 b = *(const float4*)&Bs[buf][kk][tx * 4];
            float av[4] = {a.x, a.y, a.z, a.w};
            float bv[4] = {b.x, b.y, b.z, b.w};
            #pragma unroll
            for (int r = 0; r < 4; r++)
                #pragma unroll
                for (int s = 0; s < 4; s++)
                    acc[r][s] = fmaf(av[r], bv[s], acc[r][s]);
        }
        buf ^= 1;
        if (kn < K) __syncthreads();
    }
    #pragma unroll
    for (int r = 0; r < 4; r++)
        #pragma unroll
        for (int s = 0; s < 4; s++)
            C[(size_t)(m0 + ty*4 + r) * ldc + (size_t)(n0 + tx*4 + s) * eC] = acc[r][s];
}

// z==0: deg0 self-kv (K=128); z in 1..3: deg1 slice z-1 (K=64). Embeds mask detect.
__global__ __launch_bounds__(128, 8) void skv_fused_kernel(
    const float* __restrict__ feats0, const float* __restrict__ Wskv0,
    const float* __restrict__ feats1, const float* __restrict__ Wskv1,
    const unsigned int* __restrict__ mask)
{
    if (blockIdx.z == 0 && blockIdx.x == 0 && blockIdx.y == 0 && threadIdx.x == 0) {
        int allBin = 1, allFloat = 1;
        for (int k = 0; k < 128; k++) {
            unsigned v = mask[k];
            if (v != 0u && v != 1u) allBin = 0;
            if (v != 0u && v != 0x3F800000u) allFloat = 0;
        }
        g_mask_mode = allBin ? 1 : (allFloat ? 2 : 0);
    }
    __shared__ float As[2][BK][BM + 4];
    __shared__ float Bs[2][BK][BN + 4];
    const int m0 = blockIdx.y * BM, n0 = blockIdx.x * BN;
    if (blockIdx.z == 0) {
        gemm_body<128>(feats0, Wskv0, g_skv0, 128, 1, 256, 1, m0, n0, As, Bs);
    } else {
        int m = blockIdx.z - 1;
        gemm_body<64>(feats1 + m, Wskv1, g_skv1 + m, 192, 3, 768, 3, m0, n0, As, Bs);
    }
}

// z==0: y0 (x=0..3); z in 1..3: y1 slice (x<2)
__global__ __launch_bounds__(128, 8) void out_fused_kernel(
    const float* __restrict__ Wout0, const float* __restrict__ Wout1,
    float* __restrict__ out)
{
    if (blockIdx.z != 0 && blockIdx.x >= 2) return;
    __shared__ float As[2][BK][BM + 4];
    __shared__ float Bs[2][BK][BN + 4];
    const int m0 = blockIdx.y * BM, n0 = blockIdx.x * BN;
    if (blockIdx.z == 0) {
        gemm_body<128>(g_out0, Wout0, out, 128, 1, 128, 1, m0, n0, As, Bs);
    } else {
        int m = blockIdx.z - 1;
        gemm_body<128>(g_out1 + m, Wout1, out + (size_t)NTOK * 128 + m,
                       384, 3, 192, 3, m0, n0, As, Bs);
    }
}

// ---------------- attention core: one token per 512-thread block ----------------
__global__ __launch_bounds__(512) void attn_kernel(
    const float* __restrict__ q0, const float* __restrict__ q1,
    const float* __restrict__ k0, const float* __restrict__ k1,
    const float* __restrict__ v0, const float* __restrict__ v1,
    const float* __restrict__ edges, const float* __restrict__ wbias,
    const float* __restrict__ self_bias, const float* __restrict__ null_bias,
    const float* __restrict__ nk0, const float* __restrict__ nv0,
    const float* __restrict__ nk1, const float* __restrict__ nv1,
    const float* __restrict__ hw1, const void* __restrict__ nbmask)
{
    const int i = blockIdx.x;
    const int t = threadIdx.x;

    __shared__ __align__(16) float q0s[128];
    __shared__ __align__(16) float q1s[384];
    __shared__ __align__(16) float wb[256];
    __shared__ float w1s[NH], sbS[NH], nbS[NH];
    __shared__ float totS[NH * NJ];
    __shared__ float attnS[NH * NJ];
    __shared__ const float* kp0S[NJ];
    __shared__ const float* kp1S[NJ];
    __shared__ const float* vp0S[NJ];
    __shared__ const float* vp1S[NJ];
    __shared__ int validS[NJ];
    __shared__ __align__(16) float red1[512];
    __shared__ __align__(16) float red3[512];

    // ---- stage ----
    if (t < 32) {
        ((float4*)q0s)[t] = ((const float4*)(q0 + (size_t)i * 128))[t];
    } else if (t < 128) {
        ((float4*)q1s)[t - 32] = ((const float4*)(q1 + (size_t)i * 384))[t - 32];
    } else if (t < 192) {
        ((float4*)wb)[t - 128] = ((const float4*)wbias)[t - 128];
    } else if (t < 200) {
        int h = t - 192;
        float x = hw1[h];
        float sp = (x > 20.f) ? x : log1pf(__expf(x));
        w1s[h] = sp * SCALE1;
        sbS[h] = self_bias[h];
        nbS[h] = null_bias[h];
    } else if (t >= 208 && t < 208 + NJ) {
        int j = t - 208;
        if (j == 0) {
            kp0S[0] = nk0; kp1S[0] = nk1; vp0S[0] = nv0; vp1S[0] = nv1; validS[0] = 1;
        } else if (j == 1) {
            kp0S[1] = g_skv0 + (size_t)i * 256;
            vp0S[1] = g_skv0 + (size_t)i * 256 + 128;
            kp1S[1] = g_skv1 + (size_t)i * 768;
            vp1S[1] = g_skv1 + (size_t)i * 768 + 384;
            validS[1] = 1;
        } else {
            size_t r = (size_t)i * NN + (j - 2);
            kp0S[j] = k0 + r * 128;
            kp1S[j] = k1 + r * 384;
            vp0S[j] = v0 + r * 128;
            vp1S[j] = v1 + r * 384;
            int mm = g_mask_mode;
            int mi = i * NN + (j - 2);
            int valid;
            if (mm == 1)      valid = ((const int*)nbmask)[mi] != 0;
            else if (mm == 2) valid = ((const float*)nbmask)[mi] != 0.f;
            else              valid = ((const unsigned char*)nbmask)[mi] != 0;
            validS[j] = valid;
        }
    }
    __syncthreads();

    // ---- logits: warp per j (16 warps); lane owns head lane/4, segment lane%4 ----
    {
        const int w = t >> 5, lane = t & 31;
        const int h = lane >> 2, part = lane & 3;
        const float4 qa = ((const float4*)q0s)[lane];
        const float4* q1v = (const float4*)(q1s + 12 * lane);
        const float4 qb0 = q1v[0], qb1 = q1v[1], qb2 = q1v[2];
        const float w1h = w1s[h];

        for (int j = w; j < NJ; j += 16) {
            const float4* k0p = (const float4*)kp0S[j];
            const float4* k1p = (const float4*)(kp1S[j] + 12 * lane);
            float4 ka  = k0p[lane];
            float4 kb0 = k1p[0], kb1 = k1p[1], kb2 = k1p[2];
            float s0 = dot4(qa, ka);
            float s1 = dot4(qb0, kb0) + dot4(qb1, kb1) + dot4(qb2, kb2);
            float p = s0 * SCALE0 + s1 * w1h;
            if (j >= 2) {
                const float4* ep  = (const float4*)(edges + (size_t)i * 1024 + (j - 2) * 32 + part * 8);
                const float4* wbp = (const float4*)(wb + h * 32 + part * 8);
                p += dot4(ep[0], wbp[0]) + dot4(ep[1], wbp[1]);
            }
            p += __shfl_down_sync(0xffffffffu, p, 2);
            p += __shfl_down_sync(0xffffffffu, p, 1);
            if (part == 0) {
                if (j == 1) p += sbS[h];
                if (j == 0) p += nbS[h];
                totS[h * NJ + j] = validS[j] ? p * SHAREDC : NEGV;
            }
        }
    }
    __syncthreads();

    // ---- softmax: warps 0..7, warp w = head w over 34 logits ----
    if (t < 256) {
        const int w = t >> 5, lane = t & 31;
        float x1 = totS[w * NJ + lane];
        float x2 = (lane < 2) ? totS[w * NJ + 32 + lane] : -2e9f;
        float mx = fmaxf(x1, x2);
        #pragma unroll
        for (int o = 16; o > 0; o >>= 1) mx = fmaxf(mx, __shfl_xor_sync(0xffffffffu, mx, o));
        float e1 = __expf(x1 - mx);
        float e2 = (lane < 2) ? __expf(x2 - mx) : 0.f;
        float s = e1 + e2;
        #pragma unroll
        for (int o = 16; o > 0; o >>= 1) s += __shfl_xor_sync(0xffffffffu, s, o);
        float inv = 1.f / s;
        attnS[w * NJ + lane] = e1 * inv;
        if (lane < 2) attnS[w * NJ + 32 + lane] = e2 * inv;
    }
    __syncthreads();

    // ---- V accumulation: 4 j-parity groups x 128 float4 slots, prefetch ----
    {
        const int g  = t >> 7;        // 0..3: handles j == g (mod 4)
        const int tl = t & 127;
        const bool isV1 = (tl < 96);
        const int off = isV1 ? 4 * tl : 4 * (tl - 96);
        const int hv  = isV1 ? (tl / 12) : ((tl - 96) / 4);

        float4 acc = make_float4(0.f, 0.f, 0.f, 0.f);
        float4 cur = *(const float4*)((isV1 ? vp1S[g] : vp0S[g]) + off);
        #pragma unroll 1
        for (int j = g; j < NJ; j += 4) {
            float4 nxt = make_float4(0.f, 0.f, 0.f, 0.f);
            int jn = j + 4;
            if (jn < NJ)
                nxt = *(const float4*)((isV1 ? vp1S[jn] : vp0S[jn]) + off);
            float wgt = attnS[hv * NJ + j];
            acc.x = fmaf(wgt, cur.x, acc.x);
            acc.y = fmaf(wgt, cur.y, acc.y);
            acc.z = fmaf(wgt, cur.z, acc.z);
            acc.w = fmaf(wgt, cur.w, acc.w);
            cur = nxt;
        }
        if (g == 1) ((float4*)red1)[tl] = acc;
        if (g == 3) ((float4*)red3)[tl] = acc;
        __syncthreads();
        if (g == 0) {
            float4 o = ((const float4*)red1)[tl];
            acc.x += o.x; acc.y += o.y; acc.z += o.z; acc.w += o.w;
            ((float4*)red1)[tl] = acc;
        }
        if (g == 2) {
            float4 o = ((const float4*)red3)[tl];
            acc.x += o.x; acc.y += o.y; acc.z += o.z; acc.w += o.w;
        }
        __syncthreads();
        if (g == 2) {
            float4 o = ((const float4*)red1)[tl];
            acc.x += o.x; acc.y += o.y; acc.z += o.z; acc.w += o.w;
            if (isV1) *(float4*)(g_out1 + (size_t)i * 384 + off) = acc;
            else      *(float4*)(g_out0 + (size_t)i * 128 + off) = acc;
        }
    }
}

// ---------------- launch ----------------
extern "C" void kernel_launch(void* const* d_in, const int* in_sizes, int n_in,
                              void* d_out, int out_size)
{
    const float* q0     = (const float*)d_in[0];
    const float* k0     = (const float*)d_in[1];
    const float* v0     = (const float*)d_in[2];
    const float* q1     = (const float*)d_in[3];
    const float* k1     = (const float*)d_in[4];
    const float* v1     = (const float*)d_in[5];
    const float* feats0 = (const float*)d_in[6];
    const float* feats1 = (const float*)d_in[7];
    const float* edges  = (const float*)d_in[8];
    const float* Wskv0  = (const float*)d_in[9];
    const float* Wskv1  = (const float*)d_in[10];
    const float* Wbias  = (const float*)d_in[11];
    const float* sbias  = (const float*)d_in[12];
    const float* nbias  = (const float*)d_in[13];
    const float* nk0    = (const float*)d_in[14];
    const float* nv0    = (const float*)d_in[15];
    const float* nk1    = (const float*)d_in[16];
    const float* nv1    = (const float*)d_in[17];
    const float* hw1    = (const float*)d_in[18];
    const float* Wout0  = (const float*)d_in[19];
    const float* Wout1  = (const float*)d_in[20];
    const void*  nbm    = d_in[21];
    float* out = (float*)d_out;

    skv_fused_kernel<<<dim3(256 / BN, NTOK / BM, 4), 128>>>(
        feats0, Wskv0, feats1, Wskv1, (const unsigned int*)nbm);

    attn_kernel<<<NTOK, 512>>>(q0, q1, k0, k1, v0, v1, edges, Wbias,
                               sbias, nbias, nk0, nv0, nk1, nv1, hw1, nbm);

    out_fused_kernel<<<dim3(128 / BN, NTOK / BM, 4), 128>>>(Wout0, Wout1, out);
}